// round 1
// baseline (speedup 1.0000x reference)
#include <cuda_runtime.h>

// Problem constants
#define N_TOK 16384
#define DIM   1024
#define HID   4096
#define HHALF 2048
#define NEXP  8
#define TOPK  2
#define EPSLN 1e-5f

// SGEMM tiling
#define BM 128
#define BN 128
#define BK 8
#define TM 8
#define TN 8

// ---------------- scratch (static device globals; no runtime allocation) ----
__device__ float g_xn[N_TOK * DIM];                 // LayerNorm output        (64MB)
__device__ float g_hr[N_TOK * HHALF];               // router hidden           (128MB)
__device__ float g_h[(N_TOK * TOPK) * HID];         // expert hidden, compact  (512MB)
__device__ int   g_cnt[NEXP];
__device__ int   g_off[NEXP];
__device__ int   g_fill[NEXP];
__device__ int   g_e12[N_TOK];                      // packed top-2 expert ids
__device__ float g_g1[N_TOK];
__device__ float g_g2[N_TOK];
__device__ int   g_list[N_TOK * TOPK];              // token id per routed row
__device__ float g_lgate[N_TOK * TOPK];             // gate per routed row

// ---------------- LayerNorm --------------------------------------------------
__global__ void ln_kernel(const float* __restrict__ x,
                          const float* __restrict__ gam,
                          const float* __restrict__ bet) {
    int row = blockIdx.x;
    const float* xr = x + (size_t)row * DIM;
    float s = 0.f, ss = 0.f;
    for (int i = threadIdx.x; i < DIM; i += 256) {
        float v = xr[i];
        s += v;
        ss += v * v;
    }
    __shared__ float sh[64];
    for (int o = 16; o; o >>= 1) {
        s  += __shfl_xor_sync(0xFFFFFFFFu, s,  o);
        ss += __shfl_xor_sync(0xFFFFFFFFu, ss, o);
    }
    int w = threadIdx.x >> 5, l = threadIdx.x & 31;
    if (l == 0) { sh[w] = s; sh[w + 32] = ss; }
    __syncthreads();
    if (w == 0) {
        s  = (l < 8) ? sh[l] : 0.f;
        ss = (l < 8) ? sh[l + 32] : 0.f;
        for (int o = 4; o; o >>= 1) {
            s  += __shfl_xor_sync(0xFFFFFFFFu, s,  o);
            ss += __shfl_xor_sync(0xFFFFFFFFu, ss, o);
        }
        if (l == 0) { sh[0] = s; sh[1] = ss; }
    }
    __syncthreads();
    float mu  = sh[0] * (1.0f / DIM);
    float var = sh[1] * (1.0f / DIM) - mu * mu;
    float r   = rsqrtf(var + EPSLN);
    float* xo = g_xn + (size_t)row * DIM;
    for (int i = threadIdx.x; i < DIM; i += 256)
        xo[i] = (xr[i] - mu) * r * gam[i] + bet[i];
}

// ---------------- Router GEMM1: hr = relu(xn @ r_w1 + r_b1) ------------------
// M = N_TOK, K = DIM, N = HHALF. All dims tile-exact; no bounds checks.
__global__ void __launch_bounds__(256) gemm_r1(const float* __restrict__ W,
                                               const float* __restrict__ bias) {
    __shared__ __align__(16) float As[BK][BM];
    __shared__ __align__(16) float Bs[BK][BN];
    int bm = blockIdx.y * BM, bn = blockIdx.x * BN;
    int tid = threadIdx.x;
    int arow = tid >> 1, acol = (tid & 1) * 4;
    int brow = tid >> 5, bcol = (tid & 31) * 4;
    const float* Arow = g_xn + (size_t)(bm + arow) * DIM;
    float acc[TM][TN] = {};
    for (int k0 = 0; k0 < DIM; k0 += BK) {
        float4 av = *(const float4*)(Arow + k0 + acol);
        As[acol + 0][arow] = av.x; As[acol + 1][arow] = av.y;
        As[acol + 2][arow] = av.z; As[acol + 3][arow] = av.w;
        *(float4*)&Bs[brow][bcol] =
            *(const float4*)(W + (size_t)(k0 + brow) * HHALF + bn + bcol);
        __syncthreads();
#pragma unroll
        for (int k = 0; k < BK; k++) {
            float4 a0 = *(float4*)&As[k][(tid >> 4) * TM];
            float4 a1 = *(float4*)&As[k][(tid >> 4) * TM + 4];
            float4 b0 = *(float4*)&Bs[k][(tid & 15) * TN];
            float4 b1 = *(float4*)&Bs[k][(tid & 15) * TN + 4];
            float a[8] = {a0.x, a0.y, a0.z, a0.w, a1.x, a1.y, a1.z, a1.w};
            float b[8] = {b0.x, b0.y, b0.z, b0.w, b1.x, b1.y, b1.z, b1.w};
#pragma unroll
            for (int i = 0; i < TM; i++)
#pragma unroll
                for (int j = 0; j < TN; j++) acc[i][j] += a[i] * b[j];
        }
        __syncthreads();
    }
    int tr = (tid >> 4) * TM, tc = (tid & 15) * TN;
#pragma unroll
    for (int i = 0; i < TM; i++) {
        float* crow = g_hr + (size_t)(bm + tr + i) * HHALF + bn + tc;
#pragma unroll
        for (int j = 0; j < TN; j++) {
            float v = acc[i][j] + bias[bn + tc + j];
            crow[j] = fmaxf(v, 0.f);
        }
    }
}

// ---------------- Router logits + softmax top-2 + gates ----------------------
__global__ void router_kernel(const float* __restrict__ w2,
                              const float* __restrict__ b2) {
    int warp = threadIdx.x >> 5, lane = threadIdx.x & 31;
    int t = blockIdx.x * 8 + warp;
    const float* hrow = g_hr + (size_t)t * HHALF;
    float acc[NEXP] = {};
    for (int i = lane; i < HHALF; i += 32) {
        float v = hrow[i];
        const float4* wp = (const float4*)(w2 + i * NEXP);
        float4 w0 = __ldg(wp), w1 = __ldg(wp + 1);
        acc[0] += v * w0.x; acc[1] += v * w0.y; acc[2] += v * w0.z; acc[3] += v * w0.w;
        acc[4] += v * w1.x; acc[5] += v * w1.y; acc[6] += v * w1.z; acc[7] += v * w1.w;
    }
    for (int o = 16; o; o >>= 1)
#pragma unroll
        for (int e = 0; e < NEXP; e++)
            acc[e] += __shfl_xor_sync(0xFFFFFFFFu, acc[e], o);
    if (lane == 0) {
        float l[NEXP];
#pragma unroll
        for (int e = 0; e < NEXP; e++) l[e] = acc[e] + b2[e];
        int e1 = 0;
        for (int e = 1; e < NEXP; e++) if (l[e] > l[e1]) e1 = e;
        int e2 = -1;
        for (int e = 0; e < NEXP; e++) {
            if (e == e1) continue;
            if (e2 < 0 || l[e] > l[e2]) e2 = e;
        }
        // top-2 renormalized softmax gates
        float ed  = expf(l[e2] - l[e1]);
        float inv = 1.f / (1.f + ed);
        g_e12[t] = e1 | (e2 << 8);
        g_g1[t] = inv;
        g_g2[t] = ed * inv;
        atomicAdd(&g_cnt[e1], 1);
        atomicAdd(&g_cnt[e2], 1);
    }
}

__global__ void zero_cnt_kernel() {
    if (threadIdx.x < NEXP) g_cnt[threadIdx.x] = 0;
}

__global__ void scan_kernel() {
    if (threadIdx.x == 0) {
        int s = 0;
        for (int e = 0; e < NEXP; e++) {
            g_off[e] = s;
            s += g_cnt[e];
            g_fill[e] = 0;
        }
    }
}

__global__ void place_kernel() {
    int t = blockIdx.x * 256 + threadIdx.x;
    if (t >= N_TOK) return;
    int e12 = g_e12[t];
    int e1 = e12 & 0xFF, e2 = e12 >> 8;
    int p1 = atomicAdd(&g_fill[e1], 1);
    int s1 = g_off[e1] + p1;
    g_list[s1]  = t;
    g_lgate[s1] = g_g1[t];
    int p2 = atomicAdd(&g_fill[e2], 1);
    int s2 = g_off[e2] + p2;
    g_list[s2]  = t;
    g_lgate[s2] = g_g2[t];
}

// ---------------- Expert GEMM1: h = relu(xn[list] @ e_w1[e] + e_b1[e]) -------
__global__ void __launch_bounds__(256) egemm1(const float* __restrict__ W1,
                                              const float* __restrict__ B1) {
    int e = blockIdx.z;
    int cnt = g_cnt[e];
    int bm = blockIdx.y * BM;
    if (bm >= cnt) return;
    int base = g_off[e];
    int bn = blockIdx.x * BN;
    const float* W    = W1 + (size_t)e * DIM * HID;
    const float* bias = B1 + e * HID;

    __shared__ __align__(16) float As[BK][BM];
    __shared__ __align__(16) float Bs[BK][BN];
    int tid = threadIdx.x;
    int arow = tid >> 1, acol = (tid & 1) * 4;
    int brow = tid >> 5, bcol = (tid & 31) * 4;
    int lrow = bm + arow;
    int tokA = g_list[base + ((lrow < cnt) ? lrow : 0)];
    const float* Arow = g_xn + (size_t)tokA * DIM;
    float acc[TM][TN] = {};
    for (int k0 = 0; k0 < DIM; k0 += BK) {
        float4 av = *(const float4*)(Arow + k0 + acol);
        As[acol + 0][arow] = av.x; As[acol + 1][arow] = av.y;
        As[acol + 2][arow] = av.z; As[acol + 3][arow] = av.w;
        *(float4*)&Bs[brow][bcol] =
            *(const float4*)(W + (size_t)(k0 + brow) * HID + bn + bcol);
        __syncthreads();
#pragma unroll
        for (int k = 0; k < BK; k++) {
            float4 a0 = *(float4*)&As[k][(tid >> 4) * TM];
            float4 a1 = *(float4*)&As[k][(tid >> 4) * TM + 4];
            float4 b0 = *(float4*)&Bs[k][(tid & 15) * TN];
            float4 b1 = *(float4*)&Bs[k][(tid & 15) * TN + 4];
            float a[8] = {a0.x, a0.y, a0.z, a0.w, a1.x, a1.y, a1.z, a1.w};
            float b[8] = {b0.x, b0.y, b0.z, b0.w, b1.x, b1.y, b1.z, b1.w};
#pragma unroll
            for (int i = 0; i < TM; i++)
#pragma unroll
                for (int j = 0; j < TN; j++) acc[i][j] += a[i] * b[j];
        }
        __syncthreads();
    }
    int tr = (tid >> 4) * TM, tc = (tid & 15) * TN;
#pragma unroll
    for (int i = 0; i < TM; i++) {
        int r = bm + tr + i;
        if (r >= cnt) continue;
        float* crow = g_h + (size_t)(base + r) * HID + bn + tc;
#pragma unroll
        for (int j = 0; j < TN; j++) {
            float v = acc[i][j] + bias[bn + tc + j];
            crow[j] = fmaxf(v, 0.f);
        }
    }
}

// ---------------- Expert GEMM2: out[tok] += gate * (h @ e_w2[e] + e_b2[e]) ---
__global__ void __launch_bounds__(256) egemm2(const float* __restrict__ W2,
                                              const float* __restrict__ B2,
                                              float* __restrict__ out) {
    int e = blockIdx.z;
    int cnt = g_cnt[e];
    int bm = blockIdx.y * BM;
    if (bm >= cnt) return;
    int base = g_off[e];
    int bn = blockIdx.x * BN;
    const float* W    = W2 + (size_t)e * HID * DIM;
    const float* bias = B2 + e * DIM;

    __shared__ __align__(16) float As[BK][BM];
    __shared__ __align__(16) float Bs[BK][BN];
    int tid = threadIdx.x;
    int arow = tid >> 1, acol = (tid & 1) * 4;
    int brow = tid >> 5, bcol = (tid & 31) * 4;
    int lrow = bm + arow;
    int srow = base + ((lrow < cnt) ? lrow : 0);
    const float* Arow = g_h + (size_t)srow * HID;
    float acc[TM][TN] = {};
    for (int k0 = 0; k0 < HID; k0 += BK) {
        float4 av = *(const float4*)(Arow + k0 + acol);
        As[acol + 0][arow] = av.x; As[acol + 1][arow] = av.y;
        As[acol + 2][arow] = av.z; As[acol + 3][arow] = av.w;
        *(float4*)&Bs[brow][bcol] =
            *(const float4*)(W + (size_t)(k0 + brow) * DIM + bn + bcol);
        __syncthreads();
#pragma unroll
        for (int k = 0; k < BK; k++) {
            float4 a0 = *(float4*)&As[k][(tid >> 4) * TM];
            float4 a1 = *(float4*)&As[k][(tid >> 4) * TM + 4];
            float4 b0 = *(float4*)&Bs[k][(tid & 15) * TN];
            float4 b1 = *(float4*)&Bs[k][(tid & 15) * TN + 4];
            float a[8] = {a0.x, a0.y, a0.z, a0.w, a1.x, a1.y, a1.z, a1.w};
            float b[8] = {b0.x, b0.y, b0.z, b0.w, b1.x, b1.y, b1.z, b1.w};
#pragma unroll
            for (int i = 0; i < TM; i++)
#pragma unroll
                for (int j = 0; j < TN; j++) acc[i][j] += a[i] * b[j];
        }
        __syncthreads();
    }
    int tr = (tid >> 4) * TM, tc = (tid & 15) * TN;
#pragma unroll
    for (int i = 0; i < TM; i++) {
        int r = bm + tr + i;
        if (r >= cnt) continue;
        int slot = base + r;
        int tok = g_list[slot];
        float gate = g_lgate[slot];
        float* orow = out + (size_t)tok * DIM + bn + tc;
#pragma unroll
        for (int j = 0; j < TN; j++)
            atomicAdd(&orow[j], gate * (acc[i][j] + bias[bn + tc + j]));
    }
}

// ---------------- launch ------------------------------------------------------
extern "C" void kernel_launch(void* const* d_in, const int* in_sizes, int n_in,
                              void* d_out, int out_size) {
    const float* x    = (const float*)d_in[0];
    const float* ln_g = (const float*)d_in[1];
    const float* ln_b = (const float*)d_in[2];
    const float* r_w1 = (const float*)d_in[3];
    const float* r_b1 = (const float*)d_in[4];
    const float* r_w2 = (const float*)d_in[5];
    const float* r_b2 = (const float*)d_in[6];
    const float* e_w1 = (const float*)d_in[7];
    const float* e_b1 = (const float*)d_in[8];
    const float* e_w2 = (const float*)d_in[9];
    const float* e_b2 = (const float*)d_in[10];
    float* out = (float*)d_out;

    // out = x (residual base for gate-weighted scatter adds)
    cudaMemcpyAsync(out, x, (size_t)N_TOK * DIM * sizeof(float),
                    cudaMemcpyDeviceToDevice, 0);

    zero_cnt_kernel<<<1, 32>>>();
    ln_kernel<<<N_TOK, 256>>>(x, ln_g, ln_b);
    gemm_r1<<<dim3(HHALF / BN, N_TOK / BM), 256>>>(r_w1, r_b1);
    router_kernel<<<N_TOK / 8, 256>>>(r_w2, r_b2);
    scan_kernel<<<1, 32>>>();
    place_kernel<<<N_TOK / 256, 256>>>();
    egemm1<<<dim3(HID / BN, N_TOK / BM, NEXP), 256>>>(e_w1, e_b1);
    egemm2<<<dim3(DIM / BN, N_TOK / BM, NEXP), 256>>>(e_w2, e_b2, out);
}

// round 3
// speedup vs baseline: 2.8781x; 2.8781x over previous
#include <cuda_runtime.h>
#include <cstdint>

// Problem constants
#define N_TOK 16384
#define DIM   1024
#define HID   4096
#define HHALF 2048
#define NEXP  8
#define EPSLN 1e-5f

// GEMM tiling
#define BM 128
#define BN 128
#define BKC 16          // k per pipeline chunk
#define AST 20          // A smem row stride in floats (pad 16->20: conflict-free)
#define BST 136         // B smem row stride in floats (pad 128->136: conflict-free)
#define ASZ (BM * AST)  // 2560 floats
#define BSZ (BKC * BST) // 2176 floats

// ---------------- scratch (static device globals) -----------------------------
__device__ float g_xn [(size_t)N_TOK * DIM];
__device__ float g_xnl[(size_t)N_TOK * DIM];
__device__ float g_hr [(size_t)N_TOK * HHALF];
__device__ float g_h  [(size_t)(2 * N_TOK) * HID];
__device__ float g_w1h[(size_t)DIM * HHALF];
__device__ float g_w1l[(size_t)DIM * HHALF];
__device__ float g_ew1[(size_t)NEXP * DIM * HID];
__device__ float g_ew2[(size_t)NEXP * HID * DIM];
__device__ int   g_cnt[NEXP];
__device__ int   g_off[NEXP];
__device__ int   g_fill[NEXP];
__device__ int   g_e12[N_TOK];
__device__ float g_g1[N_TOK];
__device__ float g_g2[N_TOK];
__device__ int   g_list[2 * N_TOK];
__device__ float g_lgate[2 * N_TOK];

// ---------------- helpers ------------------------------------------------------
__device__ __forceinline__ uint32_t smem_u32(const void* p) {
    uint32_t a;
    asm("{ .reg .u64 t; cvta.to.shared.u64 t, %1; cvt.u32.u64 %0, t; }" : "=r"(a) : "l"(p));
    return a;
}
__device__ __forceinline__ float rtf32(float x) {
    float r; asm("cvt.rna.tf32.f32 %0, %1;" : "=f"(r) : "f"(x)); return r;
}
#define CP16(dst, src) \
    asm volatile("cp.async.cg.shared.global [%0], [%1], 16;" :: "r"(dst), "l"(src) : "memory")
#define CP_COMMIT() asm volatile("cp.async.commit_group;" ::: "memory")
#define CP_WAIT2()  asm volatile("cp.async.wait_group 2;"  ::: "memory")
#define CP_WAIT0()  asm volatile("cp.async.wait_group 0;"  ::: "memory")

__device__ __forceinline__ void mma8(float c[4], const uint32_t a[4], const uint32_t b[2]) {
    asm volatile(
        "mma.sync.aligned.m16n8k8.row.col.f32.tf32.tf32.f32 "
        "{%0,%1,%2,%3}, {%4,%5,%6,%7}, {%8,%9}, {%0,%1,%2,%3};"
        : "+f"(c[0]), "+f"(c[1]), "+f"(c[2]), "+f"(c[3])
        : "r"(a[0]), "r"(a[1]), "r"(a[2]), "r"(a[3]), "r"(b[0]), "r"(b[1]));
}

// ---------------- LayerNorm: writes tf32 hi + lo -------------------------------
__global__ void ln_kernel(const float* __restrict__ x,
                          const float* __restrict__ gam,
                          const float* __restrict__ bet) {
    int row = blockIdx.x;
    const float* xr = x + (size_t)row * DIM;
    float s = 0.f, ss = 0.f;
    for (int i = threadIdx.x; i < DIM; i += 256) {
        float v = xr[i];
        s += v; ss += v * v;
    }
    __shared__ float sh[64];
    for (int o = 16; o; o >>= 1) {
        s  += __shfl_xor_sync(0xFFFFFFFFu, s,  o);
        ss += __shfl_xor_sync(0xFFFFFFFFu, ss, o);
    }
    int w = threadIdx.x >> 5, l = threadIdx.x & 31;
    if (l == 0) { sh[w] = s; sh[w + 32] = ss; }
    __syncthreads();
    if (w == 0) {
        s  = (l < 8) ? sh[l] : 0.f;
        ss = (l < 8) ? sh[l + 32] : 0.f;
        for (int o = 4; o; o >>= 1) {
            s  += __shfl_xor_sync(0xFFFFFFFFu, s,  o);
            ss += __shfl_xor_sync(0xFFFFFFFFu, ss, o);
        }
        if (l == 0) { sh[0] = s; sh[1] = ss; }
    }
    __syncthreads();
    float mu  = sh[0] * (1.0f / DIM);
    float var = sh[1] * (1.0f / DIM) - mu * mu;
    float r   = rsqrtf(var + EPSLN);
    for (int i = threadIdx.x; i < DIM; i += 256) {
        float v = (xr[i] - mu) * r * gam[i] + bet[i];
        float h = rtf32(v);
        g_xn [(size_t)row * DIM + i] = h;
        g_xnl[(size_t)row * DIM + i] = rtf32(v - h);
    }
}

// ---------------- weight prep ---------------------------------------------------
__global__ void split_copy(const float* __restrict__ in,
                           float* __restrict__ hi, float* __restrict__ lo) {
    size_t i = (size_t)(blockIdx.x * 256 + threadIdx.x) * 4;
    float4 v = *(const float4*)(in + i);
    float4 h, l;
    h.x = rtf32(v.x); l.x = rtf32(v.x - h.x);
    h.y = rtf32(v.y); l.y = rtf32(v.y - h.y);
    h.z = rtf32(v.z); l.z = rtf32(v.z - h.z);
    h.w = rtf32(v.w); l.w = rtf32(v.w - h.w);
    *(float4*)(hi + i) = h;
    *(float4*)(lo + i) = l;
}
__global__ void round_copy(const float* __restrict__ in, float* __restrict__ out) {
    size_t i = (size_t)(blockIdx.x * 256 + threadIdx.x) * 4;
    float4 v = *(const float4*)(in + i);
    v.x = rtf32(v.x); v.y = rtf32(v.y); v.z = rtf32(v.z); v.w = rtf32(v.w);
    *(float4*)(out + i) = v;
}

// ---------------- Router logits + softmax top-2 + gates ------------------------
__global__ void router_kernel(const float* __restrict__ w2,
                              const float* __restrict__ b2) {
    int warp = threadIdx.x >> 5, lane = threadIdx.x & 31;
    int t = blockIdx.x * 8 + warp;
    const float* hrow = g_hr + (size_t)t * HHALF;
    float acc[NEXP] = {};
    for (int i = lane; i < HHALF; i += 32) {
        float v = hrow[i];
        const float4* wp = (const float4*)(w2 + i * NEXP);
        float4 w0 = __ldg(wp), w1 = __ldg(wp + 1);
        acc[0] += v * w0.x; acc[1] += v * w0.y; acc[2] += v * w0.z; acc[3] += v * w0.w;
        acc[4] += v * w1.x; acc[5] += v * w1.y; acc[6] += v * w1.z; acc[7] += v * w1.w;
    }
    for (int o = 16; o; o >>= 1)
#pragma unroll
        for (int e = 0; e < NEXP; e++)
            acc[e] += __shfl_xor_sync(0xFFFFFFFFu, acc[e], o);
    if (lane == 0) {
        float l[NEXP];
#pragma unroll
        for (int e = 0; e < NEXP; e++) l[e] = acc[e] + b2[e];
        int e1 = 0;
        for (int e = 1; e < NEXP; e++) if (l[e] > l[e1]) e1 = e;
        int e2 = -1;
        for (int e = 0; e < NEXP; e++) {
            if (e == e1) continue;
            if (e2 < 0 || l[e] > l[e2]) e2 = e;
        }
        float ed  = expf(l[e2] - l[e1]);
        float inv = 1.f / (1.f + ed);
        g_e12[t] = e1 | (e2 << 8);
        g_g1[t] = inv;
        g_g2[t] = ed * inv;
        atomicAdd(&g_cnt[e1], 1);
        atomicAdd(&g_cnt[e2], 1);
    }
}

__global__ void zero_cnt_kernel() {
    if (threadIdx.x < NEXP) g_cnt[threadIdx.x] = 0;
}
__global__ void scan_kernel() {
    if (threadIdx.x == 0) {
        int s = 0;
        for (int e = 0; e < NEXP; e++) { g_off[e] = s; s += g_cnt[e]; g_fill[e] = 0; }
    }
}
__global__ void place_kernel() {
    int t = blockIdx.x * 256 + threadIdx.x;
    if (t >= N_TOK) return;
    int e12 = g_e12[t];
    int e1 = e12 & 0xFF, e2 = e12 >> 8;
    int s1 = g_off[e1] + atomicAdd(&g_fill[e1], 1);
    g_list[s1] = t; g_lgate[s1] = g_g1[t];
    int s2 = g_off[e2] + atomicAdd(&g_fill[e2], 1);
    g_list[s2] = t; g_lgate[s2] = g_g2[t];
}

// ---------------- tf32 mma.sync GEMM --------------------------------------------
// MODE 0: g_hr = relu((xn_hi+xn_lo) @ (w1_hi+w1_lo) + b)  [split-tf32, ~fp32 exact]
// MODE 1: g_h  = rtf32(relu(gather(g_xn) @ e_w1 + b))
// MODE 2: out += gate * (g_h @ e_w2 + b)   (atomic scatter)
template <int MODE>
__global__ void __launch_bounds__(256, (MODE == 0) ? 1 : 2)
moe_mma(const float* __restrict__ bias, float* __restrict__ out) {
    constexpr bool SPLIT = (MODE == 0);
    constexpr int Kd = (MODE == 2) ? HID : DIM;
    constexpr int Nd = (MODE == 0) ? HHALF : (MODE == 1) ? HID : DIM;
    constexpr int NC = Kd / BKC;
    constexpr int STG = SPLIT ? (2 * ASZ + 2 * BSZ) : (ASZ + BSZ);

    int bm = blockIdx.y * BM, bn = blockIdx.x * BN;
    int e = 0, cnt = N_TOK, base = 0;
    if (MODE != 0) {
        e = blockIdx.z;
        cnt = g_cnt[e];
        if (bm >= cnt) return;
        base = g_off[e];
    }
    const float* Wh;
    const float* Wl = nullptr;
    if (MODE == 0)      { Wh = g_w1h; Wl = g_w1l; }
    else if (MODE == 1)   Wh = g_ew1 + (size_t)e * DIM * HID;
    else                  Wh = g_ew2 + (size_t)e * HID * DIM;
    const float* bp = bias + ((MODE == 0) ? 0 : (MODE == 1) ? e * HID : e * DIM);

    extern __shared__ float sm[];
    uint32_t smb = smem_u32(sm);

    int tid = threadIdx.x, lane = tid & 31, wid = tid >> 5;
    int wm = (wid >> 1) * 32, wn = (wid & 1) * 64;

    // per-thread load slots
    const float* ah[2];
    const float* al[2] = {nullptr, nullptr};
    const float* bh[2];
    const float* bl[2] = {nullptr, nullptr};
    uint32_t adst[2], bdst[2];
#pragma unroll
    for (int j = 0; j < 2; j++) {
        int id = tid + 256 * j;
        int row = id >> 2, c4 = id & 3;
        adst[j] = (uint32_t)row * (AST * 4) + c4 * 16;
        int r = bm + row;
        if (MODE == 1) {
            int rr = (r < cnt) ? r : cnt - 1;
            int tok = g_list[base + rr];
            ah[j] = g_xn + (size_t)tok * DIM + c4 * 4;
        } else if (MODE == 2) {
            int rr = (r < cnt) ? r : cnt - 1;
            ah[j] = g_h + (size_t)(base + rr) * HID + c4 * 4;
        } else {
            ah[j] = g_xn  + (size_t)r * DIM + c4 * 4;
            al[j] = g_xnl + (size_t)r * DIM + c4 * 4;
        }
        int kr = id >> 5, c16 = id & 31;
        bdst[j] = (uint32_t)kr * (BST * 4) + c16 * 16;
        bh[j] = Wh + (size_t)kr * Nd + bn + c16 * 4;
        if (SPLIT) bl[j] = Wl + (size_t)kr * Nd + bn + c16 * 4;
    }

    auto load = [&](int i, int st) {
        uint32_t s0 = smb + (uint32_t)st * STG * 4;
        uint32_t b0 = s0 + (SPLIT ? 2 * ASZ * 4 : ASZ * 4);
#pragma unroll
        for (int j = 0; j < 2; j++) {
            CP16(s0 + adst[j], ah[j] + i * BKC);
            if (SPLIT) CP16(s0 + ASZ * 4 + adst[j], al[j] + i * BKC);
            CP16(b0 + bdst[j], bh[j] + (size_t)i * BKC * Nd);
            if (SPLIT) CP16(b0 + BSZ * 4 + bdst[j], bl[j] + (size_t)i * BKC * Nd);
        }
        CP_COMMIT();
    };

    float c[2][8][4] = {};
    load(0, 0); load(1, 1); load(2, 2);

    int lr = lane >> 2, lc = lane & 3;
    for (int i = 0; i < NC; i++) {
        int st = i % 3;
        if (i + 3 < NC) { CP_WAIT2(); } else { CP_WAIT0(); }
        __syncthreads();
        const float* As = sm + st * STG;
        const float* Bs = As + (SPLIT ? 2 * ASZ : ASZ);
        const uint32_t* Ab = (const uint32_t*)(As + (wm + lr) * AST + lc);
        const uint32_t* Bb = (const uint32_t*)(Bs + lc * BST + wn + lr);
#pragma unroll
        for (int ks = 0; ks < 2; ks++) {
            uint32_t a[2][4], b[8][2];
#pragma unroll
            for (int mt = 0; mt < 2; mt++) {
                a[mt][0] = Ab[(mt * 16) * AST + ks * 8];
                a[mt][1] = Ab[(mt * 16 + 8) * AST + ks * 8];
                a[mt][2] = Ab[(mt * 16) * AST + ks * 8 + 4];
                a[mt][3] = Ab[(mt * 16 + 8) * AST + ks * 8 + 4];
            }
#pragma unroll
            for (int nt = 0; nt < 8; nt++) {
                b[nt][0] = Bb[(ks * 8) * BST + nt * 8];
                b[nt][1] = Bb[(ks * 8 + 4) * BST + nt * 8];
            }
#pragma unroll
            for (int mt = 0; mt < 2; mt++)
#pragma unroll
                for (int nt = 0; nt < 8; nt++)
                    mma8(c[mt][nt], a[mt], b[nt]);
            if (SPLIT) {
                const uint32_t* Ab2 = Ab + ASZ;
                const uint32_t* Bb2 = Bb + BSZ;
                uint32_t a2[2][4], b2[8][2];
#pragma unroll
                for (int mt = 0; mt < 2; mt++) {
                    a2[mt][0] = Ab2[(mt * 16) * AST + ks * 8];
                    a2[mt][1] = Ab2[(mt * 16 + 8) * AST + ks * 8];
                    a2[mt][2] = Ab2[(mt * 16) * AST + ks * 8 + 4];
                    a2[mt][3] = Ab2[(mt * 16 + 8) * AST + ks * 8 + 4];
                }
#pragma unroll
                for (int nt = 0; nt < 8; nt++) {
                    b2[nt][0] = Bb2[(ks * 8) * BST + nt * 8];
                    b2[nt][1] = Bb2[(ks * 8 + 4) * BST + nt * 8];
                }
#pragma unroll
                for (int mt = 0; mt < 2; mt++)
#pragma unroll
                    for (int nt = 0; nt < 8; nt++) {
                        mma8(c[mt][nt], a[mt],  b2[nt]);   // hi * lo
                        mma8(c[mt][nt], a2[mt], b[nt]);    // lo * hi
                    }
            }
        }
        __syncthreads();
        if (i + 3 < NC) load(i + 3, st);
    }

    // ---------------- epilogue ----------------
#pragma unroll
    for (int mt = 0; mt < 2; mt++) {
        int r0 = bm + wm + mt * 16 + lr;
#pragma unroll
        for (int half = 0; half < 2; half++) {
            int r = r0 + half * 8;
            if (MODE == 0) {
                float* row = g_hr + (size_t)r * HHALF + bn + wn;
#pragma unroll
                for (int nt = 0; nt < 8; nt++) {
                    int col = nt * 8 + lc * 2;
                    float v0 = c[mt][nt][half * 2]     + bp[bn + wn + col];
                    float v1 = c[mt][nt][half * 2 + 1] + bp[bn + wn + col + 1];
                    row[col]     = fmaxf(v0, 0.f);
                    row[col + 1] = fmaxf(v1, 0.f);
                }
            } else if (MODE == 1) {
                if (r < cnt) {
                    float* row = g_h + (size_t)(base + r) * HID + bn + wn;
#pragma unroll
                    for (int nt = 0; nt < 8; nt++) {
                        int col = nt * 8 + lc * 2;
                        float v0 = c[mt][nt][half * 2]     + bp[bn + wn + col];
                        float v1 = c[mt][nt][half * 2 + 1] + bp[bn + wn + col + 1];
                        row[col]     = rtf32(fmaxf(v0, 0.f));
                        row[col + 1] = rtf32(fmaxf(v1, 0.f));
                    }
                }
            } else {
                if (r < cnt) {
                    int slot = base + r;
                    int tok = g_list[slot];
                    float gate = g_lgate[slot];
                    float* row = out + (size_t)tok * DIM + bn + wn;
#pragma unroll
                    for (int nt = 0; nt < 8; nt++) {
                        int col = nt * 8 + lc * 2;
                        float v0 = c[mt][nt][half * 2]     + bp[bn + wn + col];
                        float v1 = c[mt][nt][half * 2 + 1] + bp[bn + wn + col + 1];
                        atomicAdd(&row[col],     gate * v0);
                        atomicAdd(&row[col + 1], gate * v1);
                    }
                }
            }
        }
    }
}

// ---------------- launch ---------------------------------------------------------
extern "C" void kernel_launch(void* const* d_in, const int* in_sizes, int n_in,
                              void* d_out, int out_size) {
    const float* x    = (const float*)d_in[0];
    const float* ln_g = (const float*)d_in[1];
    const float* ln_b = (const float*)d_in[2];
    const float* r_w1 = (const float*)d_in[3];
    const float* r_b1 = (const float*)d_in[4];
    const float* r_w2 = (const float*)d_in[5];
    const float* r_b2 = (const float*)d_in[6];
    const float* e_w1 = (const float*)d_in[7];
    const float* e_b1 = (const float*)d_in[8];
    const float* e_w2 = (const float*)d_in[9];
    const float* e_b2 = (const float*)d_in[10];
    float* out = (float*)d_out;

    static int configured = 0;
    if (!configured) {
        cudaFuncSetAttribute(moe_mma<0>, cudaFuncAttributeMaxDynamicSharedMemorySize,
                             3 * (2 * ASZ + 2 * BSZ) * 4);
        cudaFuncSetAttribute(moe_mma<1>, cudaFuncAttributeMaxDynamicSharedMemorySize,
                             3 * (ASZ + BSZ) * 4);
        cudaFuncSetAttribute(moe_mma<2>, cudaFuncAttributeMaxDynamicSharedMemorySize,
                             3 * (ASZ + BSZ) * 4);
        configured = 1;
    }

    // residual base: out = x
    cudaMemcpyAsync(out, x, (size_t)N_TOK * DIM * sizeof(float),
                    cudaMemcpyDeviceToDevice, 0);

    zero_cnt_kernel<<<1, 32>>>();
    ln_kernel<<<N_TOK, 256>>>(x, ln_g, ln_b);

    // weight prep (tf32 rounding / splitting)
    float *w1h, *w1l, *ew1, *ew2;
    cudaGetSymbolAddress((void**)&w1h, g_w1h);
    cudaGetSymbolAddress((void**)&w1l, g_w1l);
    cudaGetSymbolAddress((void**)&ew1, g_ew1);
    cudaGetSymbolAddress((void**)&ew2, g_ew2);
    split_copy<<<(DIM * HHALF / 4) / 256, 256>>>(r_w1, w1h, w1l);
    round_copy<<<(int)(((size_t)NEXP * DIM * HID / 4) / 256), 256>>>(e_w1, ew1);
    round_copy<<<(int)(((size_t)NEXP * HID * DIM / 4) / 256), 256>>>(e_w2, ew2);

    // router path (split-tf32 GEMM -> logits -> top-2 -> dispatch lists)
    moe_mma<0><<<dim3(HHALF / BN, N_TOK / BM), 256, 3 * (2 * ASZ + 2 * BSZ) * 4>>>(r_b1, nullptr);
    router_kernel<<<N_TOK / 8, 256>>>(r_w2, r_b2);
    scan_kernel<<<1, 32>>>();
    place_kernel<<<N_TOK / 256, 256>>>();

    // expert path
    moe_mma<1><<<dim3(HID / BN, N_TOK / BM, NEXP), 256, 3 * (ASZ + BSZ) * 4>>>(e_b1, nullptr);
    moe_mma<2><<<dim3(DIM / BN, N_TOK / BM, NEXP), 256, 3 * (ASZ + BSZ) * 4>>>(e_b2, out);
}

// round 4
// speedup vs baseline: 3.2355x; 1.1242x over previous
#include <cuda_runtime.h>
#include <cstdint>

// Problem constants
#define N_TOK 16384
#define DIM   1024
#define HID   4096
#define HHALF 2048
#define NEXP  8
#define EPSLN 1e-5f

// CTA tile
#define BM 128
#define BN 256
#define BSTRD 264     // BN + 8 pad, conflict-free B frag reads

// ---------------- scratch (static device globals) -----------------------------
__device__ float g_xn [(size_t)N_TOK * DIM];
__device__ float g_xnl[(size_t)N_TOK * DIM];
__device__ float g_hr [(size_t)N_TOK * HHALF];
__device__ float g_h  [(size_t)(2 * N_TOK) * HID];
__device__ float g_y  [(size_t)(2 * N_TOK) * DIM];
__device__ float g_w1h[(size_t)DIM * HHALF];
__device__ float g_w1l[(size_t)DIM * HHALF];
__device__ float g_ew1[(size_t)NEXP * DIM * HID];
__device__ float g_ew2[(size_t)NEXP * HID * DIM];
__device__ int   g_cnt[NEXP];
__device__ int   g_off[NEXP];
__device__ int   g_fill[NEXP];
__device__ int   g_e12[N_TOK];
__device__ float g_g1[N_TOK];
__device__ float g_g2[N_TOK];
__device__ int   g_list[2 * N_TOK];
__device__ int   g_s1[N_TOK];
__device__ int   g_s2[N_TOK];

// ---------------- helpers ------------------------------------------------------
__device__ __forceinline__ uint32_t smem_u32(const void* p) {
    uint32_t a;
    asm("{ .reg .u64 t; cvta.to.shared.u64 t, %1; cvt.u32.u64 %0, t; }" : "=r"(a) : "l"(p));
    return a;
}
__device__ __forceinline__ float rtf32(float x) {
    float r; asm("cvt.rna.tf32.f32 %0, %1;" : "=f"(r) : "f"(x)); return r;
}
#define CP16(dst, src) \
    asm volatile("cp.async.cg.shared.global [%0], [%1], 16;" :: "r"(dst), "l"(src) : "memory")
#define CP_COMMIT() asm volatile("cp.async.commit_group;" ::: "memory")
#define CP_WAIT1()  asm volatile("cp.async.wait_group 1;" ::: "memory")
#define CP_WAIT0()  asm volatile("cp.async.wait_group 0;" ::: "memory")

__device__ __forceinline__ void mma8(float c[4], const uint32_t a[4], const uint32_t b[2]) {
    asm volatile(
        "mma.sync.aligned.m16n8k8.row.col.f32.tf32.tf32.f32 "
        "{%0,%1,%2,%3}, {%4,%5,%6,%7}, {%8,%9}, {%0,%1,%2,%3};"
        : "+f"(c[0]), "+f"(c[1]), "+f"(c[2]), "+f"(c[3])
        : "r"(a[0]), "r"(a[1]), "r"(a[2]), "r"(a[3]), "r"(b[0]), "r"(b[1]));
}

// ---------------- LayerNorm: writes tf32 hi + lo -------------------------------
__global__ void ln_kernel(const float* __restrict__ x,
                          const float* __restrict__ gam,
                          const float* __restrict__ bet) {
    int row = blockIdx.x;
    const float* xr = x + (size_t)row * DIM;
    float s = 0.f, ss = 0.f;
    for (int i = threadIdx.x; i < DIM; i += 256) {
        float v = xr[i];
        s += v; ss += v * v;
    }
    __shared__ float sh[64];
    for (int o = 16; o; o >>= 1) {
        s  += __shfl_xor_sync(0xFFFFFFFFu, s,  o);
        ss += __shfl_xor_sync(0xFFFFFFFFu, ss, o);
    }
    int w = threadIdx.x >> 5, l = threadIdx.x & 31;
    if (l == 0) { sh[w] = s; sh[w + 32] = ss; }
    __syncthreads();
    if (w == 0) {
        s  = (l < 8) ? sh[l] : 0.f;
        ss = (l < 8) ? sh[l + 32] : 0.f;
        for (int o = 4; o; o >>= 1) {
            s  += __shfl_xor_sync(0xFFFFFFFFu, s,  o);
            ss += __shfl_xor_sync(0xFFFFFFFFu, ss, o);
        }
        if (l == 0) { sh[0] = s; sh[1] = ss; }
    }
    __syncthreads();
    float mu  = sh[0] * (1.0f / DIM);
    float var = sh[1] * (1.0f / DIM) - mu * mu;
    float r   = rsqrtf(var + EPSLN);
    for (int i = threadIdx.x; i < DIM; i += 256) {
        float v = (xr[i] - mu) * r * gam[i] + bet[i];
        float h = rtf32(v);
        g_xn [(size_t)row * DIM + i] = h;
        g_xnl[(size_t)row * DIM + i] = rtf32(v - h);
    }
}

// ---------------- weight prep ---------------------------------------------------
__global__ void split_copy(const float* __restrict__ in,
                           float* __restrict__ hi, float* __restrict__ lo) {
    size_t i = (size_t)(blockIdx.x * 256 + threadIdx.x) * 4;
    float4 v = *(const float4*)(in + i);
    float4 h, l;
    h.x = rtf32(v.x); l.x = rtf32(v.x - h.x);
    h.y = rtf32(v.y); l.y = rtf32(v.y - h.y);
    h.z = rtf32(v.z); l.z = rtf32(v.z - h.z);
    h.w = rtf32(v.w); l.w = rtf32(v.w - h.w);
    *(float4*)(hi + i) = h;
    *(float4*)(lo + i) = l;
}
__global__ void round_copy(const float* __restrict__ in, float* __restrict__ out) {
    size_t i = (size_t)(blockIdx.x * 256 + threadIdx.x) * 4;
    float4 v = *(const float4*)(in + i);
    v.x = rtf32(v.x); v.y = rtf32(v.y); v.z = rtf32(v.z); v.w = rtf32(v.w);
    *(float4*)(out + i) = v;
}

// ---------------- Router logits + softmax top-2 + gates ------------------------
__global__ void router_kernel(const float* __restrict__ w2,
                              const float* __restrict__ b2) {
    int warp = threadIdx.x >> 5, lane = threadIdx.x & 31;
    int t = blockIdx.x * 8 + warp;
    const float* hrow = g_hr + (size_t)t * HHALF;
    float acc[NEXP] = {};
    for (int i = lane; i < HHALF; i += 32) {
        float v = hrow[i];
        const float4* wp = (const float4*)(w2 + i * NEXP);
        float4 w0 = __ldg(wp), w1 = __ldg(wp + 1);
        acc[0] += v * w0.x; acc[1] += v * w0.y; acc[2] += v * w0.z; acc[3] += v * w0.w;
        acc[4] += v * w1.x; acc[5] += v * w1.y; acc[6] += v * w1.z; acc[7] += v * w1.w;
    }
    for (int o = 16; o; o >>= 1)
#pragma unroll
        for (int e = 0; e < NEXP; e++)
            acc[e] += __shfl_xor_sync(0xFFFFFFFFu, acc[e], o);
    if (lane == 0) {
        float l[NEXP];
#pragma unroll
        for (int e = 0; e < NEXP; e++) l[e] = acc[e] + b2[e];
        int e1 = 0;
        for (int e = 1; e < NEXP; e++) if (l[e] > l[e1]) e1 = e;
        int e2 = -1;
        for (int e = 0; e < NEXP; e++) {
            if (e == e1) continue;
            if (e2 < 0 || l[e] > l[e2]) e2 = e;
        }
        float ed  = expf(l[e2] - l[e1]);
        float inv = 1.f / (1.f + ed);
        g_e12[t] = e1 | (e2 << 8);
        g_g1[t] = inv;
        g_g2[t] = ed * inv;
        atomicAdd(&g_cnt[e1], 1);
        atomicAdd(&g_cnt[e2], 1);
    }
}

__global__ void zero_cnt_kernel() {
    if (threadIdx.x < NEXP) g_cnt[threadIdx.x] = 0;
}
__global__ void scan_kernel() {
    if (threadIdx.x == 0) {
        int s = 0;
        for (int e = 0; e < NEXP; e++) { g_off[e] = s; s += g_cnt[e]; g_fill[e] = 0; }
    }
}
__global__ void place_kernel() {
    int t = blockIdx.x * 256 + threadIdx.x;
    if (t >= N_TOK) return;
    int e12 = g_e12[t];
    int e1 = e12 & 0xFF, e2 = e12 >> 8;
    int s1 = g_off[e1] + atomicAdd(&g_fill[e1], 1);
    g_list[s1] = t; g_s1[t] = s1;
    int s2 = g_off[e2] + atomicAdd(&g_fill[e2], 1);
    g_list[s2] = t; g_s2[t] = s2;
}

// ---------------- final combine: out = x + g1*y[s1] + g2*y[s2] ------------------
__global__ void combine_kernel(const float* __restrict__ x, float* __restrict__ out) {
    int t = blockIdx.x;
    int s1 = g_s1[t], s2 = g_s2[t];
    float a = g_g1[t], b = g_g2[t];
    const float4* xr = (const float4*)(x   + (size_t)t  * DIM);
    const float4* y1 = (const float4*)(g_y + (size_t)s1 * DIM);
    const float4* y2 = (const float4*)(g_y + (size_t)s2 * DIM);
    float4* o = (float4*)(out + (size_t)t * DIM);
    int i = threadIdx.x;                     // 256 threads, DIM/4 = 256
    float4 xv = xr[i], v1 = y1[i], v2 = y2[i];
    float4 r;
    r.x = xv.x + a * v1.x + b * v2.x;
    r.y = xv.y + a * v1.y + b * v2.y;
    r.z = xv.z + a * v1.z + b * v2.z;
    r.w = xv.w + a * v1.w + b * v2.w;
    o[i] = r;
}

// ---------------- tf32 mma.sync GEMM (128x256 CTA, 64x64 warp tiles) ------------
// MODE 0: g_hr = relu(split-tf32(xn @ r_w1) + b)       M=16384 N=2048 K=1024
// MODE 1: g_h  = rtf32(relu(gather(xn) @ e_w1 + b))    M=cnt   N=4096 K=1024
// MODE 2: g_y  = g_h @ e_w2 + b   (compact rows)       M=cnt   N=1024 K=4096
template <int MODE>
__global__ void __launch_bounds__(256, 1)
moe_mma(const float* __restrict__ bias) {
    constexpr bool SPLIT = (MODE == 0);
    constexpr int Kd  = (MODE == 2) ? HID : DIM;
    constexpr int Nd  = (MODE == 0) ? HHALF : (MODE == 1) ? HID : DIM;
    constexpr int BKC = SPLIT ? 16 : 32;
    constexpr int NC  = Kd / BKC;
    constexpr int AST = BKC + 4;
    constexpr int ASZ = BM * AST;            // one copy, floats
    constexpr int BSZ = BKC * BSTRD;
    constexpr int STG = (SPLIT ? 2 : 1) * (ASZ + BSZ);
    constexpr int AJ  = BKC / 8;             // A CP16 per thread per copy
    constexpr int BJ  = BKC / 4;             // B CP16 per thread per copy

    int bm = blockIdx.y * BM, bn = blockIdx.x * BN;
    int e = 0, cnt = N_TOK, base = 0;
    if (MODE != 0) {
        e = blockIdx.z;
        cnt = g_cnt[e];
        if (bm >= cnt) return;
        base = g_off[e];
    }
    const float* Wh;
    const float* Wl = nullptr;
    if (MODE == 0)      { Wh = g_w1h; Wl = g_w1l; }
    else if (MODE == 1)   Wh = g_ew1 + (size_t)e * DIM * HID;
    else                  Wh = g_ew2 + (size_t)e * HID * DIM;
    const float* bp = bias + ((MODE == 0) ? 0 : (MODE == 1) ? e * HID : e * DIM);

    extern __shared__ float sm[];
    uint32_t smb = smem_u32(sm);

    int tid = threadIdx.x, lane = tid & 31, wid = tid >> 5;
    int wm = (wid >> 2) * 64, wn = (wid & 3) * 64;

    // ---- per-thread load slots ----
    const float* ah[AJ];
    const float* al[AJ];
    const float* bh[BJ];
    const float* bl[BJ];
    uint32_t adst[AJ], bdst[BJ];
#pragma unroll
    for (int j = 0; j < AJ; j++) {
        int id = tid + 256 * j;
        int row = id / (BKC / 4), c4 = id % (BKC / 4);
        adst[j] = (uint32_t)row * (AST * 4) + c4 * 16;
        int r = bm + row;
        if (MODE == 1) {
            int rr = (r < cnt) ? r : cnt - 1;
            ah[j] = g_xn + (size_t)g_list[base + rr] * DIM + c4 * 4;
        } else if (MODE == 2) {
            int rr = (r < cnt) ? r : cnt - 1;
            ah[j] = g_h + (size_t)(base + rr) * HID + c4 * 4;
        } else {
            ah[j] = g_xn  + (size_t)r * DIM + c4 * 4;
            al[j] = g_xnl + (size_t)r * DIM + c4 * 4;
        }
    }
#pragma unroll
    for (int j = 0; j < BJ; j++) {
        int id = tid + 256 * j;
        int kr = id >> 6, c = id & 63;
        bdst[j] = (uint32_t)kr * (BSTRD * 4) + c * 16;
        bh[j] = Wh + (size_t)kr * Nd + bn + c * 4;
        if (SPLIT) bl[j] = Wl + (size_t)kr * Nd + bn + c * 4;
    }

    auto load = [&](int i, int st) {
        uint32_t s0 = smb + (uint32_t)st * STG * 4;
        uint32_t b0 = s0 + (SPLIT ? 2u : 1u) * ASZ * 4;
        int ko = i * BKC;
        size_t bko = (size_t)ko * Nd;
#pragma unroll
        for (int j = 0; j < AJ; j++) {
            CP16(s0 + adst[j], ah[j] + ko);
            if (SPLIT) CP16(s0 + ASZ * 4 + adst[j], al[j] + ko);
        }
#pragma unroll
        for (int j = 0; j < BJ; j++) {
            CP16(b0 + bdst[j], bh[j] + bko);
            if (SPLIT) CP16(b0 + BSZ * 4 + bdst[j], bl[j] + bko);
        }
        CP_COMMIT();
    };

    float c[4][8][4] = {};
    load(0, 0);
    load(1, 1);

    int lr = lane >> 2, lc = lane & 3;
    for (int i = 0; i < NC; i++) {
        int st = i % 3;
        if (i + 2 < NC) { CP_WAIT1(); } else { CP_WAIT0(); }
        __syncthreads();
        if (i + 2 < NC) load(i + 2, (i + 2) % 3);

        const uint32_t* Au = (const uint32_t*)(sm + st * STG);
        const uint32_t* Bu = Au + (SPLIT ? 2 : 1) * ASZ;
#pragma unroll
        for (int ks = 0; ks < BKC / 8; ks++) {
            uint32_t a[4][4], b[8][2];
#pragma unroll
            for (int mt = 0; mt < 4; mt++) {
                const uint32_t* ap = Au + (wm + mt * 16 + lr) * AST + ks * 8 + lc;
                a[mt][0] = ap[0];
                a[mt][1] = ap[8 * AST];
                a[mt][2] = ap[4];
                a[mt][3] = ap[8 * AST + 4];
            }
#pragma unroll
            for (int nt = 0; nt < 8; nt++) {
                const uint32_t* bpp = Bu + (ks * 8 + lc) * BSTRD + wn + nt * 8 + lr;
                b[nt][0] = bpp[0];
                b[nt][1] = bpp[4 * BSTRD];
            }
#pragma unroll
            for (int mt = 0; mt < 4; mt++)
#pragma unroll
                for (int nt = 0; nt < 8; nt++)
                    mma8(c[mt][nt], a[mt], b[nt]);
            if (SPLIT) {
                // hi * lo
                uint32_t t2[8][2];
#pragma unroll
                for (int nt = 0; nt < 8; nt++) {
                    const uint32_t* bpp = Bu + BSZ + (ks * 8 + lc) * BSTRD + wn + nt * 8 + lr;
                    t2[nt][0] = bpp[0];
                    t2[nt][1] = bpp[4 * BSTRD];
                }
#pragma unroll
                for (int mt = 0; mt < 4; mt++)
#pragma unroll
                    for (int nt = 0; nt < 8; nt++)
                        mma8(c[mt][nt], a[mt], t2[nt]);
                // lo * hi
                uint32_t a2[4][4];
#pragma unroll
                for (int mt = 0; mt < 4; mt++) {
                    const uint32_t* ap = Au + ASZ + (wm + mt * 16 + lr) * AST + ks * 8 + lc;
                    a2[mt][0] = ap[0];
                    a2[mt][1] = ap[8 * AST];
                    a2[mt][2] = ap[4];
                    a2[mt][3] = ap[8 * AST + 4];
                }
#pragma unroll
                for (int mt = 0; mt < 4; mt++)
#pragma unroll
                    for (int nt = 0; nt < 8; nt++)
                        mma8(c[mt][nt], a2[mt], b[nt]);
            }
        }
    }

    // ---------------- epilogue ----------------
#pragma unroll
    for (int mt = 0; mt < 4; mt++) {
#pragma unroll
        for (int half = 0; half < 2; half++) {
            int r = bm + wm + mt * 16 + lr + half * 8;
            if (MODE != 0 && r >= cnt) continue;
            float* row;
            if (MODE == 0)      row = g_hr + (size_t)r * HHALF;
            else if (MODE == 1) row = g_h  + (size_t)(base + r) * HID;
            else                row = g_y  + (size_t)(base + r) * DIM;
#pragma unroll
            for (int nt = 0; nt < 8; nt++) {
                int col = bn + wn + nt * 8 + lc * 2;
                float v0 = c[mt][nt][half * 2]     + bp[col];
                float v1 = c[mt][nt][half * 2 + 1] + bp[col + 1];
                float2 st2;
                if (MODE == 0) {
                    st2.x = fmaxf(v0, 0.f); st2.y = fmaxf(v1, 0.f);
                } else if (MODE == 1) {
                    st2.x = rtf32(fmaxf(v0, 0.f)); st2.y = rtf32(fmaxf(v1, 0.f));
                } else {
                    st2.x = v0; st2.y = v1;
                }
                *(float2*)(row + col) = st2;
            }
        }
    }
}

// ---------------- launch ---------------------------------------------------------
extern "C" void kernel_launch(void* const* d_in, const int* in_sizes, int n_in,
                              void* d_out, int out_size) {
    const float* x    = (const float*)d_in[0];
    const float* ln_g = (const float*)d_in[1];
    const float* ln_b = (const float*)d_in[2];
    const float* r_w1 = (const float*)d_in[3];
    const float* r_b1 = (const float*)d_in[4];
    const float* r_w2 = (const float*)d_in[5];
    const float* r_b2 = (const float*)d_in[6];
    const float* e_w1 = (const float*)d_in[7];
    const float* e_b1 = (const float*)d_in[8];
    const float* e_w2 = (const float*)d_in[9];
    const float* e_b2 = (const float*)d_in[10];
    float* out = (float*)d_out;

    // smem sizes
    const int SMEM_P = 3 * (BM * 36 + 32 * BSTRD) * 4;           // plain: 156672
    const int SMEM_S = 3 * (2 * (BM * 20) + 2 * (16 * BSTRD)) * 4; // split: 162816

    static int configured = 0;
    if (!configured) {
        cudaFuncSetAttribute(moe_mma<0>, cudaFuncAttributeMaxDynamicSharedMemorySize, SMEM_S);
        cudaFuncSetAttribute(moe_mma<1>, cudaFuncAttributeMaxDynamicSharedMemorySize, SMEM_P);
        cudaFuncSetAttribute(moe_mma<2>, cudaFuncAttributeMaxDynamicSharedMemorySize, SMEM_P);
        configured = 1;
    }

    zero_cnt_kernel<<<1, 32>>>();
    ln_kernel<<<N_TOK, 256>>>(x, ln_g, ln_b);

    // weight prep (tf32 rounding / splitting)
    float *w1h, *w1l, *ew1, *ew2;
    cudaGetSymbolAddress((void**)&w1h, g_w1h);
    cudaGetSymbolAddress((void**)&w1l, g_w1l);
    cudaGetSymbolAddress((void**)&ew1, g_ew1);
    cudaGetSymbolAddress((void**)&ew2, g_ew2);
    split_copy<<<(DIM * HHALF / 4) / 256, 256>>>(r_w1, w1h, w1l);
    round_copy<<<(int)(((size_t)NEXP * DIM * HID / 4) / 256), 256>>>(e_w1, ew1);
    round_copy<<<(int)(((size_t)NEXP * HID * DIM / 4) / 256), 256>>>(e_w2, ew2);

    // router path (split-tf32 GEMM -> logits -> top-2 -> dispatch lists)
    moe_mma<0><<<dim3(HHALF / BN, N_TOK / BM), 256, SMEM_S>>>(r_b1);
    router_kernel<<<N_TOK / 8, 256>>>(r_w2, r_b2);
    scan_kernel<<<1, 32>>>();
    place_kernel<<<N_TOK / 256, 256>>>();

    // expert path
    moe_mma<1><<<dim3(HID / BN, N_TOK / BM, NEXP), 256, SMEM_P>>>(e_b1);
    moe_mma<2><<<dim3(DIM / BN, N_TOK / BM, NEXP), 256, SMEM_P>>>(e_b2);

    // out = x + g1*y1 + g2*y2
    combine_kernel<<<N_TOK, 256>>>(x, out);
}